// round 1
// baseline (speedup 1.0000x reference)
#include <cuda_runtime.h>
#include <cuda_bf16.h>
#include <math.h>

// Problem constants
#define NN    50000
#define EE    800000
#define ET    (EE + NN)      // edges + self loops
#define FIN   128
#define HIDC  128
#define HEADS 4
#define GG    512
#define C1    (HEADS * HIDC) // 512

// ---------------- scratch (static device globals; no allocation allowed) ---
__device__ float g_h1[(size_t)NN * C1];      // x @ W1
__device__ float g_act1[(size_t)NN * C1];    // elu(agg1 + b1)
__device__ float g_h2[(size_t)NN * HIDC];    // act1 @ W2
__device__ float g_out2[(size_t)NN * HIDC];  // elu(agg2 + b2)
__device__ float g_asrc1[NN * HEADS];
__device__ float g_adst1[NN * HEADS];
__device__ float g_asrc2[NN];
__device__ float g_adst2[NN];
__device__ int   g_deg[NN];
__device__ int   g_rowptr[NN + 1];
__device__ int   g_cursor[NN];
__device__ int   g_esrc[ET];
__device__ float g_pool[GG * HIDC];
__device__ float g_cnt[GG];

// ---------------- init ------------------------------------------------------
__global__ void init_kernel() {
    int i = blockIdx.x * blockDim.x + threadIdx.x;
    int stride = gridDim.x * blockDim.x;
    for (int k = i; k < NN; k += stride) { g_deg[k] = 1; g_cursor[k] = 0; }
    for (int k = i; k < GG * HIDC; k += stride) g_pool[k] = 0.f;
    for (int k = i; k < GG; k += stride) g_cnt[k] = 0.f;
}

// ---------------- degree count ---------------------------------------------
__global__ void count_kernel(const int* __restrict__ ei) {
    int i = blockIdx.x * blockDim.x + threadIdx.x;
    if (i < EE) atomicAdd(&g_deg[ei[EE + i]], 1);
}

// ---------------- exclusive scan (single block) ----------------------------
__global__ void scan_kernel() {
    __shared__ int sm[1024];
    __shared__ int carry_s;
    int tid = threadIdx.x;
    if (tid == 0) carry_s = 0;
    __syncthreads();
    for (int base = 0; base < NN; base += 1024) {
        int carry = carry_s;
        int i = base + tid;
        int v = (i < NN) ? g_deg[i] : 0;
        sm[tid] = v;
        __syncthreads();
        for (int off = 1; off < 1024; off <<= 1) {
            int t = (tid >= off) ? sm[tid - off] : 0;
            __syncthreads();
            sm[tid] += t;
            __syncthreads();
        }
        if (i < NN) g_rowptr[i] = carry + sm[tid] - v;
        if (tid == 1023) carry_s = carry + sm[1023];
        __syncthreads();
    }
    if (tid == 0) g_rowptr[NN] = carry_s;
}

// ---------------- scatter into CSR (edges + self loops) --------------------
__global__ void scatter_kernel(const int* __restrict__ ei) {
    int i = blockIdx.x * blockDim.x + threadIdx.x;
    if (i < EE) {
        int s = ei[i];
        int d = ei[EE + i];
        int pos = g_rowptr[d] + atomicAdd(&g_cursor[d], 1);
        g_esrc[pos] = s;
    } else if (i < ET) {
        int n = i - EE;
        int pos = g_rowptr[n] + atomicAdd(&g_cursor[n], 1);
        g_esrc[pos] = n;
    }
}

// ---------------- SGEMM 128x128x16, 8x8 per thread --------------------------
__global__ __launch_bounds__(256) void sgemm_kernel(
    const float* __restrict__ A, const float* __restrict__ B,
    float* __restrict__ C, int M, int Nn, int K)
{
    const int BM = 128, BN = 128, BK = 16;
    __shared__ float As[BK][BM];
    __shared__ float Bs[BK][BN];
    int tid = threadIdx.x;
    int tx = tid % 16, ty = tid / 16;
    int rowBase = blockIdx.y * BM, colBase = blockIdx.x * BN;
    float acc[8][8];
#pragma unroll
    for (int i = 0; i < 8; i++)
#pragma unroll
        for (int j = 0; j < 8; j++) acc[i][j] = 0.f;

    for (int k0 = 0; k0 < K; k0 += BK) {
#pragma unroll
        for (int l = 0; l < 2; l++) {
            int idx = tid + l * 256;      // 0..511  (128 rows x 4 float4)
            int r = idx >> 2;
            int c4 = idx & 3;
            int gr = rowBase + r;
            float4 v = make_float4(0.f, 0.f, 0.f, 0.f);
            if (gr < M) v = *reinterpret_cast<const float4*>(&A[(size_t)gr * K + k0 + c4 * 4]);
            As[c4 * 4 + 0][r] = v.x;
            As[c4 * 4 + 1][r] = v.y;
            As[c4 * 4 + 2][r] = v.z;
            As[c4 * 4 + 3][r] = v.w;
        }
#pragma unroll
        for (int l = 0; l < 2; l++) {
            int idx = tid + l * 256;      // 0..511  (16 rows x 32 float4)
            int r = idx >> 5;
            int c4 = idx & 31;
            float4 v = *reinterpret_cast<const float4*>(&B[(size_t)(k0 + r) * Nn + colBase + c4 * 4]);
            *reinterpret_cast<float4*>(&Bs[r][c4 * 4]) = v;
        }
        __syncthreads();
#pragma unroll
        for (int kk = 0; kk < BK; kk++) {
            float a[8], b[8];
            *(float4*)&a[0] = *(float4*)&As[kk][ty * 8];
            *(float4*)&a[4] = *(float4*)&As[kk][ty * 8 + 4];
            *(float4*)&b[0] = *(float4*)&Bs[kk][tx * 8];
            *(float4*)&b[4] = *(float4*)&Bs[kk][tx * 8 + 4];
#pragma unroll
            for (int i = 0; i < 8; i++)
#pragma unroll
                for (int j = 0; j < 8; j++) acc[i][j] += a[i] * b[j];
        }
        __syncthreads();
    }
#pragma unroll
    for (int i = 0; i < 8; i++) {
        int gr = rowBase + ty * 8 + i;
        if (gr < M) {
            *(float4*)&C[(size_t)gr * Nn + colBase + tx * 8 + 0] = *(float4*)&acc[i][0];
            *(float4*)&C[(size_t)gr * Nn + colBase + tx * 8 + 4] = *(float4*)&acc[i][4];
        }
    }
}

// ---------------- attention dot products (asrc/adst per node,head) ---------
template <int H, int C>
__global__ void dots_kernel(const float* __restrict__ h,
                            const float* __restrict__ a_src,
                            const float* __restrict__ a_dst,
                            float* __restrict__ asrc, float* __restrict__ adst)
{
    int node = blockIdx.x;
    int w = threadIdx.x / 32, lane = threadIdx.x % 32;
    const float* hp = h + (size_t)node * H * C + w * C;
    float s1 = 0.f, s2 = 0.f;
#pragma unroll
    for (int i = lane; i < C; i += 32) {
        float v = hp[i];
        s1 += v * a_src[w * C + i];
        s2 += v * a_dst[w * C + i];
    }
#pragma unroll
    for (int off = 16; off; off >>= 1) {
        s1 += __shfl_down_sync(0xffffffffu, s1, off);
        s2 += __shfl_down_sync(0xffffffffu, s2, off);
    }
    if (lane == 0) {
        asrc[node * H + w] = s1;
        adst[node * H + w] = s2;
    }
}

// ---------------- block reductions (128 threads) ---------------------------
__device__ __forceinline__ float blockReduceMax128(float v, float* s) {
    int t = threadIdx.x;
    __syncthreads();
    s[t] = v;
    __syncthreads();
    if (t < 64) s[t] = fmaxf(s[t], s[t + 64]);
    __syncthreads();
    if (t < 32) {
        float x = fmaxf(s[t], s[t + 32]);
#pragma unroll
        for (int o = 16; o; o >>= 1) x = fmaxf(x, __shfl_down_sync(0xffffffffu, x, o));
        if (t == 0) s[0] = x;
    }
    __syncthreads();
    float r = s[0];
    __syncthreads();
    return r;
}

__device__ __forceinline__ float blockReduceSum128(float v, float* s) {
    int t = threadIdx.x;
    __syncthreads();
    s[t] = v;
    __syncthreads();
    if (t < 64) s[t] += s[t + 64];
    __syncthreads();
    if (t < 32) {
        float x = s[t] + s[t + 32];
#pragma unroll
        for (int o = 16; o; o >>= 1) x += __shfl_down_sync(0xffffffffu, x, o);
        if (t == 0) s[0] = x;
    }
    __syncthreads();
    float r = s[0];
    __syncthreads();
    return r;
}

// ---------------- fused attention + aggregation per dst node ---------------
// threads = C (128). Online (chunked) softmax; out = elu(acc/denom + bias).
template <int H, int C>
__global__ __launch_bounds__(C) void agg_kernel(
    const float* __restrict__ h,
    const float* __restrict__ asrc, const float* __restrict__ adst,
    const float* __restrict__ bias, float* __restrict__ out)
{
    const int CH = 1024;
    __shared__ int   s_src[CH];
    __shared__ float s_w[CH * H];
    __shared__ float s_red[C];

    int node = blockIdx.x, t = threadIdx.x;
    int beg = g_rowptr[node], end = g_rowptr[node + 1];

    float ad[H], m[H], ssum[H], acc[H];
#pragma unroll
    for (int hh = 0; hh < H; hh++) {
        ad[hh] = adst[node * H + hh];
        m[hh] = -1e30f;
        ssum[hh] = 0.f;
        acc[hh] = 0.f;
    }

    for (int cbeg = beg; cbeg < end; cbeg += CH) {
        int clen = min(CH, end - cbeg);
        // logits + local max
        float lmax[H];
#pragma unroll
        for (int hh = 0; hh < H; hh++) lmax[hh] = -1e30f;
        for (int i = t; i < clen; i += C) {
            int s = g_esrc[cbeg + i];
            s_src[i] = s;
#pragma unroll
            for (int hh = 0; hh < H; hh++) {
                float l = asrc[s * H + hh] + ad[hh];
                l = l > 0.f ? l : 0.2f * l;
                s_w[i * H + hh] = l;
                lmax[hh] = fmaxf(lmax[hh], l);
            }
        }
        float newm[H], f[H];
#pragma unroll
        for (int hh = 0; hh < H; hh++) {
            float cm = blockReduceMax128(lmax[hh], s_red);
            newm[hh] = fmaxf(m[hh], cm);
            f[hh] = __expf(m[hh] - newm[hh]);
            m[hh] = newm[hh];
        }
        // exponentiate + local sums
        float ls[H];
#pragma unroll
        for (int hh = 0; hh < H; hh++) ls[hh] = 0.f;
        for (int i = t; i < clen; i += C) {
#pragma unroll
            for (int hh = 0; hh < H; hh++) {
                float w = __expf(s_w[i * H + hh] - m[hh]);
                s_w[i * H + hh] = w;
                ls[hh] += w;
            }
        }
#pragma unroll
        for (int hh = 0; hh < H; hh++) {
            float cs = blockReduceSum128(ls[hh], s_red);
            ssum[hh] = ssum[hh] * f[hh] + cs;
            acc[hh] *= f[hh];
        }
        // aggregation: serial over chunk edges, coalesced channel gathers
#pragma unroll 2
        for (int i = 0; i < clen; i++) {
            int s = s_src[i];
            const float* hp = h + (size_t)s * (H * C);
#pragma unroll
            for (int hh = 0; hh < H; hh++) {
                acc[hh] += s_w[i * H + hh] * hp[hh * C + t];
            }
        }
        __syncthreads();
    }
#pragma unroll
    for (int hh = 0; hh < H; hh++) {
        float v = acc[hh] / ssum[hh] + bias[hh * C + t];
        out[(size_t)node * H * C + hh * C + t] = v > 0.f ? v : expm1f(v);
    }
}

// ---------------- pooling ---------------------------------------------------
__global__ void pool_kernel(const int* __restrict__ batch) {
    int i = blockIdx.x * blockDim.x + threadIdx.x;
    if (i < NN * HIDC) {
        int node = i >> 7, c = i & 127;
        int g = batch[node];
        atomicAdd(&g_pool[g * HIDC + c], g_out2[i]);
        if (c == 0) atomicAdd(&g_cnt[g], 1.0f);
    }
}

__global__ void final_kernel(const float* __restrict__ Wl,
                             const float* __restrict__ bl,
                             float* __restrict__ out)
{
    __shared__ float s_red[128];
    int g = blockIdx.x, t = threadIdx.x;
    float c = fmaxf(g_cnt[g], 1.0f);
    float v = g_pool[g * HIDC + t] / c * Wl[t];
    float r = blockReduceSum128(v, s_red);
    if (t == 0) out[g] = r + bl[0];
}

// ---------------- launch ----------------------------------------------------
extern "C" void kernel_launch(void* const* d_in, const int* in_sizes, int n_in,
                              void* d_out, int out_size)
{
    const float* x       = (const float*)d_in[0];
    const int*   ei      = (const int*)  d_in[1];
    const int*   batch   = (const int*)  d_in[2];
    const float* W1      = (const float*)d_in[3];
    const float* a_src1  = (const float*)d_in[4];
    const float* a_dst1  = (const float*)d_in[5];
    const float* b1      = (const float*)d_in[6];
    const float* W2      = (const float*)d_in[7];
    const float* a_src2  = (const float*)d_in[8];
    const float* a_dst2  = (const float*)d_in[9];
    const float* b2      = (const float*)d_in[10];
    const float* Wl      = (const float*)d_in[11];
    const float* bl      = (const float*)d_in[12];
    float* out = (float*)d_out;

    float *p_h1, *p_act1, *p_h2, *p_out2, *p_asrc1, *p_adst1, *p_asrc2, *p_adst2;
    cudaGetSymbolAddress((void**)&p_h1,    g_h1);
    cudaGetSymbolAddress((void**)&p_act1,  g_act1);
    cudaGetSymbolAddress((void**)&p_h2,    g_h2);
    cudaGetSymbolAddress((void**)&p_out2,  g_out2);
    cudaGetSymbolAddress((void**)&p_asrc1, g_asrc1);
    cudaGetSymbolAddress((void**)&p_adst1, g_adst1);
    cudaGetSymbolAddress((void**)&p_asrc2, g_asrc2);
    cudaGetSymbolAddress((void**)&p_adst2, g_adst2);

    // build CSR (counting sort by dst, self loops included)
    init_kernel<<<512, 256>>>();
    count_kernel<<<(EE + 255) / 256, 256>>>(ei);
    scan_kernel<<<1, 1024>>>();
    scatter_kernel<<<(ET + 255) / 256, 256>>>(ei);

    // layer 1
    {
        dim3 grid((C1 + 127) / 128, (NN + 127) / 128);
        sgemm_kernel<<<grid, 256>>>(x, W1, p_h1, NN, C1, FIN);
    }
    dots_kernel<HEADS, HIDC><<<NN, 32 * HEADS>>>(p_h1, a_src1, a_dst1, p_asrc1, p_adst1);
    agg_kernel<HEADS, HIDC><<<NN, HIDC>>>(p_h1, p_asrc1, p_adst1, b1, p_act1);

    // layer 2
    {
        dim3 grid((HIDC + 127) / 128, (NN + 127) / 128);
        sgemm_kernel<<<grid, 256>>>(p_act1, W2, p_h2, NN, HIDC, C1);
    }
    dots_kernel<1, HIDC><<<NN, 32>>>(p_h2, a_src2, a_dst2, p_asrc2, p_adst2);
    agg_kernel<1, HIDC><<<NN, HIDC>>>(p_h2, p_asrc2, p_adst2, b2, p_out2);

    // pooling + linear head
    pool_kernel<<<((size_t)NN * HIDC + 255) / 256, 256>>>(batch);
    final_kernel<<<GG, HIDC>>>(Wl, bl, out);
}